// round 1
// baseline (speedup 1.0000x reference)
#include <cuda_runtime.h>
#include <math.h>

#define BB 8
#define TT 2048
#define SS 3
#define HH 12
#define WW 6
#define LL 512
#define NC 48          // channels in x: S*H + 3*N_NOISE = 36 + 12
#define NN 4
#define RR 4
#define NTAP 9

// ---------------- device globals (scratch; no allocation allowed) ----------
__device__ float g_envmean[BB][SS * HH];      // per-batch mean over T of env channels
__device__ float g_w[BB][NN][NTAP];           // normalized gaussian weights per (b, noise)

// ---------------- stats prepass --------------------------------------------
// grid = (B), block = 384. Column sums of x over T, then derive env means and
// gaussian weights.
__global__ void stats_kernel(const float* __restrict__ x) {
    __shared__ float partial[8][NC];
    int b = blockIdx.x;
    int tid = threadIdx.x;            // 0..383
    int c = tid % NC;                 // column
    int r = tid / NC;                 // 0..7
    float s = 0.f;
    const float* xb = x + (size_t)b * TT * NC;
    for (int t = r; t < TT; t += 8) s += xb[(size_t)t * NC + c];
    partial[r][c] = s;
    __syncthreads();
    if (tid < NC) {
        float tot = 0.f;
#pragma unroll
        for (int k = 0; k < 8; k++) tot += partial[k][tid];
        float mean = tot * (1.0f / TT);
        if (tid < SS * HH) {
            g_envmean[b][tid] = mean;
        } else {
            int rem = tid - SS * HH;          // 0..11
            if (rem % 3 == 2) {
                int i = rem / 3;              // noise index
                float sigma = fmaxf(mean, 0.001f);
                float inv2s2 = 0.5f / (sigma * sigma);
                float ws[NTAP];
                float wsum = 0.f;
#pragma unroll
                for (int j = 0; j < NTAP; j++) {
                    float k = (float)(j - RR);
                    ws[j] = expf(-k * k * inv2s2);
                    wsum += ws[j];
                }
                float inv = 1.0f / wsum;
#pragma unroll
                for (int j = 0; j < NTAP; j++) g_w[b][i][j] = ws[j] * inv;
            }
        }
    }
}

// ---------------- lats kernel ----------------------------------------------
// out[b,t, s*6+w, l] = sum_h (x[b,t,s*12+h] - envmean[b,s*12+h]) * LT[s*12+h, s*6+w, l]
// grid: (L/128, T/256, B*S); block: 192 threads (6 warps; warp = one w, lanes = 32 float4 along l)
#define LCHUNK 128
#define TTILE 16
#define TILES_PER_BLOCK 16

__global__ __launch_bounds__(192) void lats_kernel(
    const float* __restrict__ x,
    const float* __restrict__ LT,
    float* __restrict__ out)
{
    __shared__ float s_lat[HH * WW * LCHUNK];   // 36,864 B
    __shared__ float s_env[TTILE][HH];

    const int lc = blockIdx.x;                  // 0..3
    const int tg = blockIdx.y;                  // 0..7
    const int bs = blockIdx.z;
    const int b  = bs / SS;
    const int s  = bs % SS;
    const int tid = threadIdx.x;

    // Load 12x6x128 latents chunk for this segment into smem (float4)
    const int NV = HH * WW * (LCHUNK / 4);      // 2304
    for (int q = tid; q < NV; q += 192) {
        int hw = q / (LCHUNK / 4);
        int v  = q % (LCHUNK / 4);
        int h = hw / WW, w = hw % WW;
        size_t gidx = (((size_t)(s * HH + h)) * (SS * WW) + (s * WW + w)) * LL
                      + (size_t)lc * LCHUNK + v * 4;
        float4 val = *(const float4*)&LT[gidx];
        *(float4*)&s_lat[q * 4] = val;
    }

    const int w  = tid / 32;
    const int l4 = tid % 32;

    // Preload this thread's env-mean row pointer
    const float* em = &g_envmean[b][s * HH];

    __syncthreads();

    for (int tile = 0; tile < TILES_PER_BLOCK; ++tile) {
        const int t0 = tg * (TILES_PER_BLOCK * TTILE) + tile * TTILE;

        // Load env tile: 16 t x 12 h, mean-subtracted. One element per thread.
        {
            int ett = tid / HH;   // 0..15
            int eh  = tid % HH;
            float v = x[((size_t)(b * TT) + (t0 + ett)) * NC + s * HH + eh] - em[eh];
            s_env[ett][eh] = v;
        }
        __syncthreads();

        float4 acc[TTILE];
#pragma unroll
        for (int ttr = 0; ttr < TTILE; ttr++) acc[ttr] = make_float4(0.f, 0.f, 0.f, 0.f);

#pragma unroll
        for (int h = 0; h < HH; h++) {
            float4 lv = *(const float4*)&s_lat[(h * WW + w) * LCHUNK + l4 * 4];
#pragma unroll
            for (int ttr = 0; ttr < TTILE; ttr++) {
                float e = s_env[ttr][h];
                acc[ttr].x = fmaf(e, lv.x, acc[ttr].x);
                acc[ttr].y = fmaf(e, lv.y, acc[ttr].y);
                acc[ttr].z = fmaf(e, lv.z, acc[ttr].z);
                acc[ttr].w = fmaf(e, lv.w, acc[ttr].w);
            }
        }

#pragma unroll
        for (int ttr = 0; ttr < TTILE; ttr++) {
            size_t o = (((size_t)(b * TT + t0 + ttr)) * (SS * WW) + (s * WW + w)) * LL
                       + (size_t)lc * LCHUNK + l4 * 4;
            *(float4*)&out[o] = acc[ttr];
        }
        __syncthreads();   // protect s_env for next tile
    }
}

// ---------------- noise kernel ---------------------------------------------
// out[b,t,p] = sum_j w[b,i,j] * (mu[b,tj] + sig[b,tj] * eps[b,tj,p]),
// tj = reflect(t + j - 4). One float4 along p per thread.
template<int P>
__global__ __launch_bounds__(256) void noise_kernel(
    const float* __restrict__ x,
    const float* __restrict__ eps,
    float* __restrict__ out,
    int noise_i)
{
    constexpr int P4 = P / 4;
    int gid = blockIdx.x * blockDim.x + threadIdx.x;
    int total = BB * TT * P4;
    if (gid >= total) return;
    int p4 = gid % P4;
    int t  = (gid / P4) % TT;
    int b  = gid / (P4 * TT);

    const float* wr = g_w[b][noise_i];
    const float* xb = x + (size_t)b * TT * NC + SS * HH + 3 * noise_i;
    const float* eb = eps + (size_t)b * TT * P + (size_t)p4 * 4;

    float4 acc = make_float4(0.f, 0.f, 0.f, 0.f);
#pragma unroll
    for (int j = 0; j < NTAP; j++) {
        int idx = t + j - RR;
        idx = (idx < 0) ? -idx : idx;
        idx = (idx >= TT) ? (2 * TT - 2 - idx) : idx;
        float wj = wr[j];
        float mu = xb[(size_t)idx * NC];
        float sg = xb[(size_t)idx * NC + 1];
        float4 e = *(const float4*)&eb[(size_t)idx * P];
        acc.x = fmaf(wj, fmaf(sg, e.x, mu), acc.x);
        acc.y = fmaf(wj, fmaf(sg, e.y, mu), acc.y);
        acc.z = fmaf(wj, fmaf(sg, e.z, mu), acc.z);
        acc.w = fmaf(wj, fmaf(sg, e.w, mu), acc.w);
    }
    *(float4*)&out[(size_t)gid * 4] = acc;
}

// ---------------- launch ----------------------------------------------------
extern "C" void kernel_launch(void* const* d_in, const int* in_sizes, int n_in,
                              void* d_out, int out_size) {
    const float* x  = (const float*)d_in[0];
    const float* LT = (const float*)d_in[1];
    const float* e0 = (const float*)d_in[2];
    const float* e1 = (const float*)d_in[3];
    const float* e2 = (const float*)d_in[4];
    const float* e3 = (const float*)d_in[5];
    float* out = (float*)d_out;

    // Output layout: lats | n0 | n1 | n2 | n3
    const size_t LATS = (size_t)BB * TT * (SS * WW) * LL;   // 150,994,944
    const size_t N0   = (size_t)BB * TT * 16;               // 262,144
    const size_t N1   = (size_t)BB * TT * 64;               // 1,048,576
    const size_t N2   = (size_t)BB * TT * 256;              // 4,194,304

    stats_kernel<<<BB, 384>>>(x);

    dim3 lgrid(LL / LCHUNK, TT / (TILES_PER_BLOCK * TTILE), BB * SS);  // 4 x 8 x 24
    lats_kernel<<<lgrid, 192>>>(x, LT, out);

    {
        int total = BB * TT * (16 / 4);
        noise_kernel<16><<<(total + 255) / 256, 256>>>(x, e0, out + LATS, 0);
    }
    {
        int total = BB * TT * (64 / 4);
        noise_kernel<64><<<(total + 255) / 256, 256>>>(x, e1, out + LATS + N0, 1);
    }
    {
        int total = BB * TT * (256 / 4);
        noise_kernel<256><<<(total + 255) / 256, 256>>>(x, e2, out + LATS + N0 + N1, 2);
    }
    {
        int total = BB * TT * (1024 / 4);
        noise_kernel<1024><<<(total + 255) / 256, 256>>>(x, e3, out + LATS + N0 + N1 + N2, 3);
    }
}